// round 17
// baseline (speedup 1.0000x reference)
#include <cuda_runtime.h>
#include <cuda_bf16.h>
#include <float.h>
#include <limits.h>
#include <stdint.h>

// Problem shape (fixed by the dataset): Q=256, D=768, N=400000.
#define DDIM   768
#define MAXQ   256
#define MAXN   400000
#define CAND   32

// GEMM tiling
#define NT      128                  // N cols per CTA
#define KC      64                   // K per chunk (64 int8 = 64B per row)
#define NUMK    (DDIM / KC)          // 12
#define THREADS 512
#define APITCH  80                   // bytes per A smem row (16B multiple, ldmatrix conflict-free)
#define BPITCH  80
#define A_SZ    (256 * APITCH)       // 20480
#define B_SZ    (NT * BPITCH)        // 10240
#define STG     (A_SZ + B_SZ)        // 30720
#define NSTAGE  4
#define DYN_SMEM (NSTAGE * STG)      // 122880

// Scratch (allocations are banned -> __device__ globals)
__device__ __align__(16) float         g_qn  [MAXQ * DDIM];                  // L1-normalized queries (fp32)
__device__ __align__(16) int8_t        g_qi8 [MAXQ * DDIM];                  // per-row-scaled int8 queries
__device__ __align__(16) int8_t        g_ei8 [(size_t)MAXN * DDIM];         // int8 emb, TRANSPOSED [n][k] (~307MB)
__device__ __align__(16) __nv_bfloat16 g_sims[(size_t)MAXQ * (size_t)MAXN]; // bf16 raw int scores (~205MB)
__device__ unsigned int g_emax_bits;
__device__ float        g_escale;

// ---------------------------------------------------------------------------
// emb scale estimation: reset -> sampled max -> finalize
// ---------------------------------------------------------------------------
__global__ void einit_kernel() { g_emax_bits = 0u; }

__global__ void esample_kernel(const float* __restrict__ emb, int N, int D) {
    int r   = (blockIdx.x >> 2) * 8;        // rows 0,8,...  (96 rows sampled)
    int seg = blockIdx.x & 3;
    if (r >= D) return;
    const float* row = emb + (size_t)r * N;
    int lo = (int)(((long long)N * seg) / 4);
    int hi = (int)(((long long)N * (seg + 1)) / 4);
    float m = 0.f;
    for (int i = lo + threadIdx.x; i < hi; i += blockDim.x)
        m = fmaxf(m, fabsf(row[i]));
    #pragma unroll
    for (int o = 16; o > 0; o >>= 1)
        m = fmaxf(m, __shfl_xor_sync(0xffffffffu, m, o));
    __shared__ float wm[8];
    if ((threadIdx.x & 31) == 0) wm[threadIdx.x >> 5] = m;
    __syncthreads();
    if (threadIdx.x == 0) {
        float t = 0.f;
        int nw = (blockDim.x + 31) >> 5;
        for (int i = 0; i < nw; i++) t = fmaxf(t, wm[i]);
        atomicMax(&g_emax_bits, __float_as_uint(t));
    }
}

__global__ void efinal_kernel() {
    float m = __uint_as_float(g_emax_bits);
    g_escale = 127.0f / (1.25f * fmaxf(m, 1e-20f));
}

// ---------------------------------------------------------------------------
// int8 quantize+pack helper
// ---------------------------------------------------------------------------
__device__ __forceinline__ uint32_t qpack4(float a, float b, float c, float d, float S) {
    uint32_t r0, r1, r2, r3;
    asm("cvt.rni.sat.s8.f32 %0, %1;" : "=r"(r0) : "f"(a * S));
    asm("cvt.rni.sat.s8.f32 %0, %1;" : "=r"(r1) : "f"(b * S));
    asm("cvt.rni.sat.s8.f32 %0, %1;" : "=r"(r2) : "f"(c * S));
    asm("cvt.rni.sat.s8.f32 %0, %1;" : "=r"(r3) : "f"(d * S));
    return __byte_perm(__byte_perm(r0, r1, 0x0040),
                       __byte_perm(r2, r3, 0x0040), 0x5410);
}

// ---------------------------------------------------------------------------
// Kernel 1: L1-normalize queries -> fp32 (rescore) + per-row-scaled int8 (GEMM)
// ---------------------------------------------------------------------------
__global__ void normq_kernel(const float* __restrict__ q, int Q) {
    int row = blockIdx.x;
    int tid = threadIdx.x;

    if (row >= Q) {   // pad rows so the M=256 tile is harmless
        for (int d = tid; d < DDIM; d += 256) {
            g_qn [(size_t)row * DDIM + d] = 0.f;
            g_qi8[(size_t)row * DDIM + d] = 0;
        }
        return;
    }

    float s = 0.f, mx = 0.f;
    for (int d = tid; d < DDIM; d += 256) {
        float v = q[(size_t)row * DDIM + d];
        s  += fabsf(v);
        mx  = fmaxf(mx, fabsf(v));
    }
    #pragma unroll
    for (int o = 16; o > 0; o >>= 1) {
        s  += __shfl_xor_sync(0xffffffffu, s, o);
        mx  = fmaxf(mx, __shfl_xor_sync(0xffffffffu, mx, o));
    }
    __shared__ float ws[8], wmx[8];
    __shared__ float inv, qs;
    if ((tid & 31) == 0) { ws[tid >> 5] = s; wmx[tid >> 5] = mx; }
    __syncthreads();
    if (tid == 0) {
        float t = 0.f, m = 0.f;
        #pragma unroll
        for (int i = 0; i < 8; i++) { t += ws[i]; m = fmaxf(m, wmx[i]); }
        inv = 1.f / fmaxf(t, 1e-12f);
        qs  = (m > 0.f) ? (127.0f / m) : 0.f;   // per-row positive scale: rank-invariant
    }
    __syncthreads();

    float iv = inv, sc = qs;
    for (int d = tid; d < DDIM; d += 256) {
        float raw = q[(size_t)row * DDIM + d];
        g_qn[(size_t)row * DDIM + d] = raw * iv;
        int r;
        asm("cvt.rni.sat.s8.f32 %0, %1;" : "=r"(r) : "f"(raw * sc));
        g_qi8[(size_t)row * DDIM + d] = (int8_t)r;
    }
}

// ---------------------------------------------------------------------------
// Kernel 2: quantize + TRANSPOSE emb fp32[768][N] -> int8 g_ei8[N][768]
// Block: 32 n-columns, full K. Coalesced reads (128B/warp) and writes (uint4).
// ---------------------------------------------------------------------------
#define TPITCH 784   // 16B multiple, breaks worst bank patterns
__global__ void convert_kernel(const float* __restrict__ emb, int N) {
    __shared__ int8_t tile[32 * TPITCH];
    int n0   = blockIdx.x * 32;
    int lane = threadIdx.x & 31;
    int w    = threadIdx.x >> 5;    // 8 warps
    float S  = g_escale;
    int n    = n0 + lane;
    bool inb = (n < N);

    // read 4 k-rows per iteration, pack 4 k-bytes, store uint32 to tile[n][k]
    for (int k0 = w * 4; k0 < DDIM; k0 += 32) {
        float f0 = 0.f, f1 = 0.f, f2 = 0.f, f3 = 0.f;
        if (inb) {
            f0 = emb[(size_t)(k0 + 0) * N + n];
            f1 = emb[(size_t)(k0 + 1) * N + n];
            f2 = emb[(size_t)(k0 + 2) * N + n];
            f3 = emb[(size_t)(k0 + 3) * N + n];
        }
        *(uint32_t*)&tile[lane * TPITCH + k0] = qpack4(f0, f1, f2, f3, S);
    }
    __syncthreads();

    // write 32 rows x 768B contiguous (48 uint4 per row), 6 units per thread
    #pragma unroll
    for (int i = 0; i < 6; i++) {
        int idx  = threadIdx.x + i * 256;
        int row  = idx / 48;
        int unit = idx % 48;
        uint4 v = *(uint4*)&tile[row * TPITCH + unit * 16];
        if (n0 + row < N)
            *(uint4*)(g_ei8 + (size_t)(n0 + row) * DDIM + unit * 16) = v;
    }
}

// ---------------------------------------------------------------------------
// cp.async helpers
// ---------------------------------------------------------------------------
__device__ __forceinline__ void cp_async16(uint32_t dst, const void* src, int srcsize) {
    asm volatile("cp.async.ca.shared.global [%0], [%1], 16, %2;"
                 :: "r"(dst), "l"(src), "r"(srcsize) : "memory");
}
#define CP_COMMIT() asm volatile("cp.async.commit_group;" ::: "memory")
#define CP_WAIT2()  asm volatile("cp.async.wait_group 2;" ::: "memory")

// ---------------------------------------------------------------------------
// Kernel 3: int8 IMMA GEMM  sims[256,N] = qi8[256,768] @ ei8[N,768]^T
// CTA tile 256x128, K-chunk 64, 512 threads (16 warps 4Mx4N, warp tile 64x32),
// 4-stage cp.async ring (depth-3 prefetch), no conversion in the mainloop.
// Output = bf16(raw int score) — bf16 because scores reach ~8e4 > fp16 max.
// ---------------------------------------------------------------------------
__global__ void __launch_bounds__(THREADS)
gemm_i8_kernel(int N) {
    extern __shared__ __align__(16) char smem[];

    const int tid  = threadIdx.x;
    const int lane = tid & 31;
    const int wid  = tid >> 5;      // 0..15
    const int wm   = wid & 3;       // M block (64 rows)
    const int wn   = wid >> 2;      // N block (32 cols)
    const int nBase = blockIdx.x * NT;
    const uint32_t smem_base = (uint32_t)__cvta_generic_to_shared(smem);

    int acc[4][4][4];
    #pragma unroll
    for (int i = 0; i < 4; i++)
        #pragma unroll
        for (int j = 0; j < 4; j++)
            #pragma unroll
            for (int r = 0; r < 4; r++) acc[i][j][r] = 0;

    // --- stage issue: A = 1024 16B units (2/thread), B = 512 units (1/thread) ---
    auto issue_stage = [&](int c, int slot) {
        const int kBase = c * KC;
        const uint32_t aS = smem_base + slot * STG;
        const uint32_t bS = aS + A_SZ;
        #pragma unroll
        for (int i = 0; i < 2; i++) {
            int idx  = tid + i * 512;
            int row  = idx >> 2;           // 0..255
            int unit = idx & 3;
            cp_async16(aS + row * APITCH + unit * 16,
                       g_qi8 + (size_t)row * DDIM + kBase + unit * 16, 16);
        }
        {
            int row  = tid >> 2;           // 0..127
            int unit = tid & 3;
            int gn   = nBase + row;
            const int8_t* src = g_ei8 + (size_t)gn * DDIM + kBase + unit * 16;
            cp_async16(bS + row * BPITCH + unit * 16, src, (gn < N) ? 16 : 0);
        }
    };

    auto compute = [&](int slot) {
        char* As = smem + slot * STG;
        char* Bs = As + A_SZ;
        #pragma unroll
        for (int ks = 0; ks < 2; ++ks) {
            uint32_t b[4][2];
            #pragma unroll
            for (int ni = 0; ni < 4; ++ni) {
                const char* p = Bs + (wn * 32 + ni * 8 + (lane & 7)) * BPITCH
                                   + ks * 32 + ((lane >> 3) & 1) * 16;
                uint32_t addr = (uint32_t)__cvta_generic_to_shared(p);
                asm volatile("ldmatrix.sync.aligned.m8n8.x2.shared.b16 {%0,%1}, [%2];"
                             : "=r"(b[ni][0]), "=r"(b[ni][1]) : "r"(addr));
            }
            #pragma unroll
            for (int mi = 0; mi < 4; ++mi) {
                uint32_t a[4];
                const char* p = As + (wm * 64 + mi * 16 + (lane & 15)) * APITCH
                                   + ks * 32 + (lane >> 4) * 16;
                uint32_t addr = (uint32_t)__cvta_generic_to_shared(p);
                asm volatile("ldmatrix.sync.aligned.m8n8.x4.shared.b16 {%0,%1,%2,%3}, [%4];"
                             : "=r"(a[0]), "=r"(a[1]), "=r"(a[2]), "=r"(a[3]) : "r"(addr));
                #pragma unroll
                for (int ni = 0; ni < 4; ++ni)
                    asm volatile(
                        "mma.sync.aligned.m16n8k32.row.col.s32.s8.s8.s32 "
                        "{%0,%1,%2,%3}, {%4,%5,%6,%7}, {%8,%9}, {%0,%1,%2,%3};"
                        : "+r"(acc[mi][ni][0]), "+r"(acc[mi][ni][1]),
                          "+r"(acc[mi][ni][2]), "+r"(acc[mi][ni][3])
                        : "r"(a[0]), "r"(a[1]), "r"(a[2]), "r"(a[3]),
                          "r"(b[ni][0]), "r"(b[ni][1]));
            }
        }
    };

    // ---- prologue: fill 3 stages (one commit group each) ----
    #pragma unroll
    for (int s = 0; s < NSTAGE - 1; ++s) {
        if (s < NUMK) issue_stage(s, s);
        CP_COMMIT();
    }

    // ---- mainloop: wait_group 2 frees stage c; always commit once/iter ----
    for (int c = 0; c < NUMK; ++c) {
        CP_WAIT2();
        __syncthreads();              // all threads' copies for stage c visible;
                                      // also: everyone done reading slot (c-1)%4
        if (c + NSTAGE - 1 < NUMK)
            issue_stage(c + NSTAGE - 1, (c + NSTAGE - 1) & (NSTAGE - 1));
        CP_COMMIT();                  // empty group in tail keeps FIFO count exact
        compute(c & (NSTAGE - 1));
    }

    // ---- epilogue: s32 -> bf16 raw scores ----
    const int rBase = wm * 64 + (lane >> 2);
    const int cBase = wn * 32 + (lane & 3) * 2;
    const bool even = ((N & 1) == 0);
    #pragma unroll
    for (int mi = 0; mi < 4; ++mi) {
        int r0 = rBase + mi * 16;
        int r1 = r0 + 8;
        #pragma unroll
        for (int ni = 0; ni < 4; ++ni) {
            int gcol = nBase + cBase + ni * 8;
            if (gcol + 1 < N && even) {
                __nv_bfloat162 v01 = __floats2bfloat162_rn((float)acc[mi][ni][0], (float)acc[mi][ni][1]);
                __nv_bfloat162 v23 = __floats2bfloat162_rn((float)acc[mi][ni][2], (float)acc[mi][ni][3]);
                *(__nv_bfloat162*)(g_sims + (size_t)r0 * N + gcol) = v01;
                *(__nv_bfloat162*)(g_sims + (size_t)r1 * N + gcol) = v23;
            } else {
                if (gcol < N) {
                    g_sims[(size_t)r0 * N + gcol] = __float2bfloat16_rn((float)acc[mi][ni][0]);
                    g_sims[(size_t)r1 * N + gcol] = __float2bfloat16_rn((float)acc[mi][ni][2]);
                }
                if (gcol + 1 < N) {
                    g_sims[(size_t)r0 * N + gcol + 1] = __float2bfloat16_rn((float)acc[mi][ni][1]);
                    g_sims[(size_t)r1 * N + gcol + 1] = __float2bfloat16_rn((float)acc[mi][ni][3]);
                }
            }
        }
    }
}

// ---------------------------------------------------------------------------
// Kernel 4: masked top-32 candidates from bf16 scores, exact fp32 rescore, top-4
// Tie-break matches jax.lax.top_k: equal value -> lower index wins.
// ---------------------------------------------------------------------------
__global__ void topk_rescore_kernel(const float* __restrict__ emb,
                                    const int* __restrict__ startp,
                                    const int* __restrict__ endp,
                                    float* __restrict__ out, int N, int Q) {
    int q = blockIdx.x;
    if (q >= Q) return;
    int tid = threadIdx.x;
    int start = startp[0];
    int end   = endp[0];

    const __nv_bfloat16* __restrict__ row = g_sims + (size_t)q * N;

    // per-thread top-4 (strict > keeps lowest index)
    float bv[4] = {-FLT_MAX, -FLT_MAX, -FLT_MAX, -FLT_MAX};
    int   bi[4] = {INT_MAX, INT_MAX, INT_MAX, INT_MAX};
    for (int n = tid; n < N; n += 256) {
        if (n >= start && n < end) continue;
        float v = __bfloat162float(row[n]);
        if (v > bv[3]) {
            bv[3] = v; bi[3] = n;
            #pragma unroll
            for (int p = 3; p > 0; p--) {
                if (bv[p] > bv[p-1]) {
                    float tv = bv[p-1]; bv[p-1] = bv[p]; bv[p] = tv;
                    int   ti = bi[p-1]; bi[p-1] = bi[p]; bi[p] = ti;
                }
            }
        }
    }

    __shared__ float sv[256 * 4];
    __shared__ int   si[256 * 4];
    #pragma unroll
    for (int j = 0; j < 4; j++) { sv[tid * 4 + j] = bv[j]; si[tid * 4 + j] = bi[j]; }
    __syncthreads();

    __shared__ int   candIdx[CAND];
    __shared__ float candVal[CAND];
    if (tid == 0) {
        float rv[CAND]; int ri[CAND];
        #pragma unroll
        for (int i = 0; i < CAND; i++) { rv[i] = -FLT_MAX; ri[i] = INT_MAX; }
        for (int t = 0; t < 256 * 4; t++) {
            float v = sv[t]; int idx = si[t];
            if (idx == INT_MAX) continue;
            if (v > rv[CAND-1] || (v == rv[CAND-1] && idx < ri[CAND-1])) {
                rv[CAND-1] = v; ri[CAND-1] = idx;
                #pragma unroll
                for (int p = CAND-1; p > 0; p--) {
                    if (rv[p] > rv[p-1] || (rv[p] == rv[p-1] && ri[p] < ri[p-1])) {
                        float tv = rv[p-1]; rv[p-1] = rv[p]; rv[p] = tv;
                        int   ti = ri[p-1]; ri[p-1] = ri[p]; ri[p] = ti;
                    }
                }
            }
        }
        #pragma unroll
        for (int i = 0; i < CAND; i++) candIdx[i] = ri[i];
    }
    __syncthreads();

    // exact fp32 rescore: 32 candidates x 8 lanes each
    int c = tid >> 3;
    int l = tid & 7;
    int idx = candIdx[c];
    float s = 0.f;
    if (idx >= 0 && idx < N) {
        const float* __restrict__ qrow = g_qn + (size_t)q * DDIM;
        for (int d = l; d < DDIM; d += 8)
            s += qrow[d] * emb[(size_t)d * N + idx];
    }
    #pragma unroll
    for (int o = 4; o > 0; o >>= 1)
        s += __shfl_down_sync(0xffffffffu, s, o, 8);
    if (l == 0) candVal[c] = (idx >= 0 && idx < N) ? s : -FLT_MAX;
    __syncthreads();

    if (tid == 0) {
        float fv[4] = {-FLT_MAX, -FLT_MAX, -FLT_MAX, -FLT_MAX};
        int   fi[4] = {INT_MAX, INT_MAX, INT_MAX, INT_MAX};
        for (int cc = 0; cc < CAND; cc++) {
            float v = candVal[cc]; int ix = candIdx[cc];
            if (ix == INT_MAX) continue;
            if (v > fv[3] || (v == fv[3] && ix < fi[3])) {
                fv[3] = v; fi[3] = ix;
                #pragma unroll
                for (int p = 3; p > 0; p--) {
                    if (fv[p] > fv[p-1] || (fv[p] == fv[p-1] && fi[p] < fi[p-1])) {
                        float tv = fv[p-1]; fv[p-1] = fv[p]; fv[p] = tv;
                        int   ti = fi[p-1]; fi[p-1] = fi[p]; fi[p] = ti;
                    }
                }
            }
        }
        #pragma unroll
        for (int j = 0; j < 4; j++) {
            out[(size_t)q * 4 + j]                 = fv[j];         // values
            out[(size_t)Q * 4 + (size_t)q * 4 + j] = (float)fi[j];  // indices
        }
    }
}

// ---------------------------------------------------------------------------
extern "C" void kernel_launch(void* const* d_in, const int* in_sizes, int n_in,
                              void* d_out, int out_size) {
    const float* query = (const float*)d_in[0];   // [Q, 768]
    const float* emb   = (const float*)d_in[1];   // [768, N]
    const int* startp  = (const int*)d_in[2];
    const int* endp    = (const int*)d_in[3];
    float* out = (float*)d_out;

    int Q = in_sizes[0] / DDIM;
    int N = in_sizes[1] / DDIM;
    if (Q <= 0 || N <= 0) return;
    if (Q > MAXQ || N > MAXN) return;

    cudaFuncSetAttribute(gemm_i8_kernel,
                         cudaFuncAttributeMaxDynamicSharedMemorySize, DYN_SMEM);

    einit_kernel<<<1, 1>>>();
    esample_kernel<<<384, 256>>>(emb, N, DDIM);
    efinal_kernel<<<1, 1>>>();

    normq_kernel<<<MAXQ, 256>>>(query, Q);

    convert_kernel<<<(N + 31) / 32, 256>>>(emb, N);

    int gridN = (N + NT - 1) / NT;
    gemm_i8_kernel<<<gridN, THREADS, DYN_SMEM>>>(N);

    topk_rescore_kernel<<<Q, 256>>>(emb, startp, endp, out, N, Q);
}